// round 4
// baseline (speedup 1.0000x reference)
#include <cuda_runtime.h>
#include <math.h>

#define PI_D 3.141592653589793238462643383279502884

// ---------------- constant / scratch device globals ----------------
__device__ double g_lg[64];            // log(k!)
__device__ double g_wq[128];           // SOFT quadrature weights
__device__ float2 g_tw128[128];        // e^{-2pi i t/128}
__device__ float2 g_e40f[40];          // e^{+2pi i t/40}

__device__ float  g_ws2 [210*128];     // [lmh][j]
__device__ float  g_dinv[40*5530];     // [b][t]
__device__ float2 g_y   [400*512];     // [lmf][i*32+o]
__device__ float2 g_xf  [20*128*256];  // [m][j][zi]
__device__ float2 g_xl  [210*256];     // [lmh][zi]
__device__ float2 g_zl  [5530*512];    // [t][z*32+o]

__device__ const int c_T[21] = {0,1,7,22,50,95,161,252,372,525,715,946,1222,1547,
                                1925,2360,2856,3417,4047,4750,5530};

__device__ double dpow_int(double x, int e) { double r = 1.0; for (int i = 0; i < e; i++) r *= x; return r; }

__device__ double wig_pow(int l, int m, int n, double cb, double sb) {
    int s0 = max(0, n - m), s1 = min(l + n, l - m);
    if (s1 < s0) return 0.0;
    double pref = 0.5 * (g_lg[l+m] + g_lg[l-m] + g_lg[l+n] + g_lg[l-n]);
    double C = exp(pref - (g_lg[l+n-s0] + g_lg[s0] + g_lg[m-n+s0] + g_lg[l-m-s0]));
    double sg = ((m - n + s0) & 1) ? -1.0 : 1.0;
    int A = 2*l + n - m - 2*s0, B = m - n + 2*s0;
    double cbA = dpow_int(cb, A), sbB = dpow_int(sb, B);
    double ci = 1.0 / (cb * cb), s2 = sb * sb;
    double val = 0.0;
    for (int s = s0; s <= s1; s++) {
        val += sg * C * cbA * sbB;
        C  *= (double)((l + n - s) * (l - m - s)) / (double)((s + 1) * (m - n + s + 1));
        sg = -sg; cbA *= ci; sbB *= s2;
    }
    return val;
}

// ---------------- setup kernels ----------------
__global__ void k_init() {
    int t = threadIdx.x;  // 128
    if (t == 0) {
        double a = 0.0; g_lg[0] = 0.0;
        for (int k = 1; k < 64; k++) { a += log((double)k); g_lg[k] = a; }
    }
    {
        double th = PI_D * (2*t + 1) / 256.0;
        double s = 0.0;
        for (int k = 0; k < 64; k++) s += sin((2*k + 1) * th) / (double)(2*k + 1);
        g_wq[t] = (2.0 / 64.0) * sin(th) * s;
        double ang = 2.0 * PI_D * t / 128.0;
        g_tw128[t] = make_float2((float)cos(ang), (float)(-sin(ang)));
    }
    if (t < 40) {
        double ang = 2.0 * PI_D * t / 40.0;
        g_e40f[t] = make_float2((float)cos(ang), (float)sin(ang));
    }
}

// fused ws2 + dinv: per-task coefficient precompute once, 3 dinv tasks per block
__global__ void k_sd() {
    __shared__ double scoef[3][24];
    int blk = blockIdx.x;
    int tid = threadIdx.x;
    if (blk < 210) {
        // ---- ws2 task: lmh = blk, n = 0 ----
        int lmh = blk;
        int l = 0; while ((l + 1) * (l + 2) / 2 <= lmh) l++;
        int m = lmh - l * (l + 1) / 2;
        int s1 = l - m;
        if (tid == 0) {
            double pref = 0.5 * (g_lg[l+m] + g_lg[l-m]) + g_lg[l];
            double C = exp(pref - (g_lg[l] + g_lg[m] + g_lg[l-m]));
            double sg = (m & 1) ? -1.0 : 1.0;
            for (int s = 0; s <= s1; s++) {
                scoef[0][s] = sg * C;
                C *= (double)((l - s) * (l - m - s)) / (double)((s + 1) * (m + s + 1));
                sg = -sg;
            }
        }
        __syncthreads();
        int j = tid;                          // 0..127
        double th = PI_D * (2*j + 1) / 256.0;
        double cb = cos(0.5 * th), sb = sin(0.5 * th);
        double cbA = dpow_int(cb, 2*l - m), sbB = dpow_int(sb, m);
        double ci = 1.0 / (cb * cb), s2 = sb * sb;
        double val = 0.0;
        for (int s = 0; s <= s1; s++) { val += scoef[0][s] * cbA * sbB; cbA *= ci; sbB *= s2; }
        g_ws2[lmh * 128 + j] = (float)(val * g_wq[j]);
    } else {
        // ---- dinv: 3 tasks per block ----
        int t0 = (blk - 210) * 3;
        if (tid < 3 && t0 + tid < 5530) {
            int t = t0 + tid;
            int l = 0; while (c_T[l + 1] <= t) l++;
            int r = t - c_T[l];
            int m = r / (2*l + 1);
            int n = r % (2*l + 1) - l;
            int s0 = max(0, n - m), s1 = min(l + n, l - m);
            double pref = 0.5 * (g_lg[l+m] + g_lg[l-m] + g_lg[l+n] + g_lg[l-n]);
            double C = exp(pref - (g_lg[l+n-s0] + g_lg[s0] + g_lg[m-n+s0] + g_lg[l-m-s0]));
            double sg = ((m - n + s0) & 1) ? -1.0 : 1.0;
            for (int s = s0; s <= s1; s++) {
                scoef[tid][s - s0] = sg * C;
                C *= (double)((l + n - s) * (l - m - s)) / (double)((s + 1) * (m - n + s + 1));
                sg = -sg;
            }
        }
        __syncthreads();
        int sub = tid / 40, b = tid % 40;
        int t = t0 + sub;
        if (sub < 3 && t < 5530) {
            int l = 0; while (c_T[l + 1] <= t) l++;
            int r = t - c_T[l];
            int m = r / (2*l + 1);
            int n = r % (2*l + 1) - l;
            int s0 = max(0, n - m), s1 = min(l + n, l - m);
            double th = PI_D * (2*b + 1) / 80.0;
            double cb = cos(0.5 * th), sb = sin(0.5 * th);
            int A0 = 2*l + n - m - 2*s0, B0 = m - n + 2*s0;
            double cbA = dpow_int(cb, A0), sbB = dpow_int(sb, B0);
            double ci = 1.0 / (cb * cb), s2 = sb * sb;
            double val = 0.0;
            int nt = s1 - s0;
            for (int s = 0; s <= nt; s++) { val += scoef[sub][s] * cbA * sbB; cbA *= ci; sbB *= s2; }
            g_dinv[b * 5530 + t] = (float)(val * (double)(2*l + 1));
        }
    }
}

// y[lmf][io] : F_k column computed in-block, then kernel dot
__global__ void k_y(const float* __restrict__ ker) {
    __shared__ float2 sFk[24];
    int lmf = blockIdx.x, io = threadIdx.x;                   // 400 x 512
    int l = 0; while ((l + 1) * (l + 1) <= lmf) l++;
    int m = lmf - l * l - l;
    if (io < 24) {
        double beta  = (io / 8 + 1) * (PI_D / 24.0);
        double alpha = (io % 8) * (PI_D / 4.0);
        double cb = cos(0.5 * beta), sb = sin(0.5 * beta);
        double d = wig_pow(l, m, 0, cb, sb);
        double sn, cn; sincos(-(double)m * alpha, &sn, &cn);
        sFk[io] = make_float2((float)(d * cn), (float)(d * sn));
    }
    __syncthreads();
    const float sc = 0.008164965809277261f;                   // 1/sqrt(15000)
    float ar = 0.f, ai = 0.f;
    #pragma unroll
    for (int p = 0; p < 24; p++) {
        float k = ker[io * 24 + p];
        ar = fmaf(k, sFk[p].x, ar);
        ai = fmaf(k, sFk[p].y, ai);
    }
    g_y[lmf * 512 + io] = make_float2(sc * ar, sc * ai);
}

// ---------------- main pipeline ----------------
// block = (j, zi-tile of 32). Rows staged in shared, lane=row, tw broadcast.
__global__ void kx1(const float* __restrict__ x) {
    __shared__ float  xs[32][129];
    __shared__ float2 stw[128];
    int tid = threadIdx.x;
    int j = blockIdx.x;                       // 0..127
    int zi0 = blockIdx.y * 32;
    if (tid < 128) stw[tid] = g_tw128[tid];
    // load 32 rows x 128 floats, coalesced
    for (int i = tid; i < 4096; i += 256) {
        int r = i >> 7, c = i & 127;
        xs[r][c] = x[((size_t)(zi0 + r) * 128 + j) * 128 + c];
    }
    __syncthreads();
    int w = tid >> 5, l = tid & 31;
    for (int m = w; m < 20; m += 8) {
        float re = 0.f, im = 0.f;
        int idx = 0;
        #pragma unroll 8
        for (int a = 0; a < 128; a++) {
            float xv = xs[l][a];
            float2 t = stw[idx];
            re = fmaf(xv, t.x, re);
            im = fmaf(xv, t.y, im);
            idx = (idx + m) & 127;
        }
        g_xf[(m * 128 + j) * 256 + zi0 + l] = make_float2(re, im);
    }
}

__global__ void kx2() {
    __shared__ float sw[128];
    int lmh = blockIdx.x, zi = threadIdx.x;                   // 210 x 256
    if (zi < 128) sw[zi] = g_ws2[lmh * 128 + zi];
    __syncthreads();
    int l = 0; while ((l + 1) * (l + 2) / 2 <= lmh) l++;
    int m = lmh - l * (l + 1) / 2;
    const float2* base = g_xf + m * 128 * 256;
    float ar = 0.f, ai = 0.f;
    for (int j = 0; j < 128; j++) {
        float w = sw[j];
        float2 v = base[j * 256 + zi];
        ar = fmaf(w, v.x, ar);
        ai = fmaf(w, v.y, ai);
    }
    g_xl[lmh * 256 + zi] = make_float2(ar, ai);
}

__global__ void kx3() {
    __shared__ float2 sx[256];
    __shared__ float2 sy[512];
    int t = blockIdx.x, tid = threadIdx.x;                    // 5530 x 512
    int l = 0; while (c_T[l + 1] <= t) l++;
    int r = t - c_T[l];
    int m = r / (2*l + 1), ni = r % (2*l + 1);
    int lmh = l * (l + 1) / 2 + m;
    int lmf = l * l + ni;
    if (tid < 256) sx[tid] = g_xl[lmh * 256 + tid];
    sy[tid] = g_y[lmf * 512 + tid];
    __syncthreads();
    int z = tid >> 5, o = tid & 31;
    float ar = 0.f, ai = 0.f;
    #pragma unroll
    for (int i = 0; i < 16; i++) {
        float2 xv = sx[z * 16 + i];
        float2 yv = sy[i * 32 + o];
        ar += xv.x * yv.x + xv.y * yv.y;      // x * conj(y)
        ai += xv.y * yv.x - xv.x * yv.y;
    }
    g_zl[t * 512 + tid] = make_float2(ar, ai);
}

// fused synthesis: single b per block, dinv row in shared, parity-paired gamma DFT
__global__ void __launch_bounds__(320) kx4(float* __restrict__ out, const float* __restrict__ bias) {
    __shared__ float  sDinv[5530];
    __shared__ float2 sOm[39 * 8];
    __shared__ float2 sS[2][20 * 8];          // [parity][gp][zol]
    __shared__ float2 se[40];
    int tid = threadIdx.x;
    int b = blockIdx.x;                       // b fastest -> L2 reuse of zl across b
    int zo0 = blockIdx.y * 8;
    if (tid < 40) se[tid] = g_e40f[tid];
    for (int i = tid; i < 5530; i += 320) sDinv[i] = g_dinv[b * 5530 + i];
    int nidx = tid >> 3, zol = tid & 7;
    float f[40];
    #pragma unroll
    for (int g = 0; g < 40; g++) f[g] = 0.f;
    __syncthreads();

    for (int m = 0; m < 20; m++) {
        // ---- stage 1: Om[n][zo] = sum_l dinv[l,m,n] * zl[l,m,n][zo]
        if (nidx < 39) {
            int n = nidx - 19;
            int an = n < 0 ? -n : n;
            int lmin = m > an ? m : an;
            float orr = 0.f, oii = 0.f;
            for (int l = lmin; l < 20; l++) {
                int tt = c_T[l] + m * (2*l + 1) + (n + l);
                float d = sDinv[tt];
                float2 zv = g_zl[tt * 512 + zo0 + zol];
                orr = fmaf(d, zv.x, orr);
                oii = fmaf(d, zv.y, oii);
            }
            sOm[nidx * 8 + zol] = make_float2(orr, oii);
        }
        __syncthreads();
        // ---- stage 2: parity partial sums  S_par[gp] = sum_{n parity} Om[n] e^{i n gp}
        {
            int par = nidx >= 20 ? 1 : 0;
            int gp = nidx - 20 * par;
            int cnt = 19 + par;               // even n: 19 terms, odd n: 20 terms
            int nn = 1 - par;                 // Om slot
            int idx = ((par ? 21 : 22) * gp) % 40;
            int step = (2 * gp) % 40;
            float sr = 0.f, si = 0.f;
            for (int k = 0; k < cnt; k++) {
                float2 e = se[idx];
                float2 om = sOm[nn * 8 + zol];
                sr += om.x * e.x - om.y * e.y;
                si += om.x * e.y + om.y * e.x;
                nn += 2;
                idx += step; if (idx >= 40) idx -= 40;
            }
            sS[par][gp * 8 + zol] = make_float2(sr, si);
        }
        __syncthreads();
        // ---- stage 3: f[a][g] += w_m Re( e^{ima} G[g] ),  G[gp]=Se+So, G[gp+20]=Se-So
        {
            int a = nidx;
            float2 e = se[(m * a) % 40];
            float w = (m == 0) ? 1.f : 2.f;
            float wc = w * e.x, ws = w * e.y;
            #pragma unroll
            for (int gp = 0; gp < 20; gp++) {
                float2 s0 = sS[0][gp * 8 + zol];
                float2 s1 = sS[1][gp * 8 + zol];
                float pr = s0.x + s1.x, pi = s0.y + s1.y;
                float qr = s0.x - s1.x, qi = s0.y - s1.y;
                f[gp]      += wc * pr - ws * pi;
                f[gp + 20] += wc * qr - ws * qi;
            }
        }
        __syncthreads();
    }

    // ---- write out: out[zo][b][a][g] + bias[o]
    int zo = zo0 + zol;
    int a = nidx;
    float bv = bias[zo & 31];
    float* op = out + ((size_t)zo * 40 + b) * 1600 + a * 40;
    float4* op4 = (float4*)op;
    #pragma unroll
    for (int g4 = 0; g4 < 10; g4++) {
        op4[g4] = make_float4(f[4*g4] + bv, f[4*g4 + 1] + bv, f[4*g4 + 2] + bv, f[4*g4 + 3] + bv);
    }
}

// ---------------- launch ----------------
extern "C" void kernel_launch(void* const* d_in, const int* in_sizes, int n_in,
                              void* d_out, int out_size) {
    const float* x    = (const float*)d_in[0];
    const float* ker  = (const float*)d_in[1];
    const float* bias = (const float*)d_in[2];
    float* out = (float*)d_out;

    k_init<<<1, 128>>>();
    k_sd  <<<210 + 1844, 128>>>();
    k_y   <<<400, 512>>>(ker);

    kx1<<<dim3(128, 8), 256>>>(x);
    kx2<<<210, 256>>>();
    kx3<<<5530, 512>>>();
    kx4<<<dim3(40, 64), 320>>>(out, bias);
}

// round 5
// speedup vs baseline: 1.2335x; 1.2335x over previous
#include <cuda_runtime.h>
#include <math.h>

#define PI_D 3.141592653589793238462643383279502884

// ---------------- constant / scratch device globals ----------------
__device__ double g_lg[64];
__device__ double g_wq[128];
__device__ float2 g_tw128[128];
__device__ float2 g_e40f[40];

__device__ float  g_ws2 [210*128];
__device__ float  g_dinv[40*5530];
__device__ float2 g_y   [400*512];
__device__ float2 g_xf  [20*128*256];
__device__ float2 g_xl  [210*256];
__device__ float2 g_zl  [5530*512];

__device__ const int c_T[21] = {0,1,7,22,50,95,161,252,372,525,715,946,1222,1547,
                                1925,2360,2856,3417,4047,4750,5530};

__device__ double dpow_int(double x, int e) { double r = 1.0; for (int i = 0; i < e; i++) r *= x; return r; }

__device__ double wig_pow(int l, int m, int n, double cb, double sb) {
    int s0 = max(0, n - m), s1 = min(l + n, l - m);
    if (s1 < s0) return 0.0;
    double pref = 0.5 * (g_lg[l+m] + g_lg[l-m] + g_lg[l+n] + g_lg[l-n]);
    double C = exp(pref - (g_lg[l+n-s0] + g_lg[s0] + g_lg[m-n+s0] + g_lg[l-m-s0]));
    double sg = ((m - n + s0) & 1) ? -1.0 : 1.0;
    int A = 2*l + n - m - 2*s0, B = m - n + 2*s0;
    double cbA = dpow_int(cb, A), sbB = dpow_int(sb, B);
    double ci = 1.0 / (cb * cb), s2 = sb * sb;
    double val = 0.0;
    for (int s = s0; s <= s1; s++) {
        val += sg * C * cbA * sbB;
        C  *= (double)((l + n - s) * (l - m - s)) / (double)((s + 1) * (m - n + s + 1));
        sg = -sg; cbA *= ci; sbB *= s2;
    }
    return val;
}

// ---------------- setup kernels ----------------
__global__ void k_init() {
    int t = threadIdx.x;  // 128
    if (t == 0) {
        double a = 0.0; g_lg[0] = 0.0;
        for (int k = 1; k < 64; k++) { a += log((double)k); g_lg[k] = a; }
    }
    {
        double th = PI_D * (2*t + 1) / 256.0;
        double s = 0.0;
        for (int k = 0; k < 64; k++) s += sin((2*k + 1) * th) / (double)(2*k + 1);
        g_wq[t] = (2.0 / 64.0) * sin(th) * s;
        double ang = 2.0 * PI_D * t / 128.0;
        g_tw128[t] = make_float2((float)cos(ang), (float)(-sin(ang)));
    }
    if (t < 40) {
        double ang = 2.0 * PI_D * t / 40.0;
        g_e40f[t] = make_float2((float)cos(ang), (float)sin(ang));
    }
}

__global__ void k_sd() {
    __shared__ double scoef[3][24];
    int blk = blockIdx.x;
    int tid = threadIdx.x;
    if (blk < 210) {
        int lmh = blk;
        int l = 0; while ((l + 1) * (l + 2) / 2 <= lmh) l++;
        int m = lmh - l * (l + 1) / 2;
        int s1 = l - m;
        if (tid == 0) {
            double pref = 0.5 * (g_lg[l+m] + g_lg[l-m]) + g_lg[l];
            double C = exp(pref - (g_lg[l] + g_lg[m] + g_lg[l-m]));
            double sg = (m & 1) ? -1.0 : 1.0;
            for (int s = 0; s <= s1; s++) {
                scoef[0][s] = sg * C;
                C *= (double)((l - s) * (l - m - s)) / (double)((s + 1) * (m + s + 1));
                sg = -sg;
            }
        }
        __syncthreads();
        int j = tid;
        double th = PI_D * (2*j + 1) / 256.0;
        double cb = cos(0.5 * th), sb = sin(0.5 * th);
        double cbA = dpow_int(cb, 2*l - m), sbB = dpow_int(sb, m);
        double ci = 1.0 / (cb * cb), s2 = sb * sb;
        double val = 0.0;
        for (int s = 0; s <= s1; s++) { val += scoef[0][s] * cbA * sbB; cbA *= ci; sbB *= s2; }
        g_ws2[lmh * 128 + j] = (float)(val * g_wq[j]);
    } else {
        int t0 = (blk - 210) * 3;
        if (tid < 3 && t0 + tid < 5530) {
            int t = t0 + tid;
            int l = 0; while (c_T[l + 1] <= t) l++;
            int r = t - c_T[l];
            int m = r / (2*l + 1);
            int n = r % (2*l + 1) - l;
            int s0 = max(0, n - m), s1 = min(l + n, l - m);
            double pref = 0.5 * (g_lg[l+m] + g_lg[l-m] + g_lg[l+n] + g_lg[l-n]);
            double C = exp(pref - (g_lg[l+n-s0] + g_lg[s0] + g_lg[m-n+s0] + g_lg[l-m-s0]));
            double sg = ((m - n + s0) & 1) ? -1.0 : 1.0;
            for (int s = s0; s <= s1; s++) {
                scoef[tid][s - s0] = sg * C;
                C *= (double)((l + n - s) * (l - m - s)) / (double)((s + 1) * (m - n + s + 1));
                sg = -sg;
            }
        }
        __syncthreads();
        int sub = tid / 40, b = tid % 40;
        int t = t0 + sub;
        if (sub < 3 && t < 5530) {
            int l = 0; while (c_T[l + 1] <= t) l++;
            int r = t - c_T[l];
            int m = r / (2*l + 1);
            int n = r % (2*l + 1) - l;
            int s0 = max(0, n - m), s1 = min(l + n, l - m);
            double th = PI_D * (2*b + 1) / 80.0;
            double cb = cos(0.5 * th), sb = sin(0.5 * th);
            int A0 = 2*l + n - m - 2*s0, B0 = m - n + 2*s0;
            double cbA = dpow_int(cb, A0), sbB = dpow_int(sb, B0);
            double ci = 1.0 / (cb * cb), s2 = sb * sb;
            double val = 0.0;
            int nt = s1 - s0;
            for (int s = 0; s <= nt; s++) { val += scoef[sub][s] * cbA * sbB; cbA *= ci; sbB *= s2; }
            g_dinv[b * 5530 + t] = (float)(val * (double)(2*l + 1));
        }
    }
}

__global__ void k_y(const float* __restrict__ ker) {
    __shared__ float2 sFk[24];
    int lmf = blockIdx.x, io = threadIdx.x;                   // 400 x 512
    int l = 0; while ((l + 1) * (l + 1) <= lmf) l++;
    int m = lmf - l * l - l;
    if (io < 24) {
        double beta  = (io / 8 + 1) * (PI_D / 24.0);
        double alpha = (io % 8) * (PI_D / 4.0);
        double cb = cos(0.5 * beta), sb = sin(0.5 * beta);
        double d = wig_pow(l, m, 0, cb, sb);
        double sn, cn; sincos(-(double)m * alpha, &sn, &cn);
        sFk[io] = make_float2((float)(d * cn), (float)(d * sn));
    }
    __syncthreads();
    const float sc = 0.008164965809277261f;
    float ar = 0.f, ai = 0.f;
    #pragma unroll
    for (int p = 0; p < 24; p++) {
        float k = ker[io * 24 + p];
        ar = fmaf(k, sFk[p].x, ar);
        ai = fmaf(k, sFk[p].y, ai);
    }
    g_y[lmf * 512 + io] = make_float2(sc * ar, sc * ai);
}

// ---------------- main pipeline ----------------
__global__ void kx1(const float* __restrict__ x) {
    __shared__ float  xs[32][129];
    __shared__ float2 stw[128];
    int tid = threadIdx.x;
    int j = blockIdx.x;
    int zi0 = blockIdx.y * 32;
    if (tid < 128) stw[tid] = g_tw128[tid];
    for (int i = tid; i < 4096; i += 256) {
        int r = i >> 7, c = i & 127;
        xs[r][c] = x[((size_t)(zi0 + r) * 128 + j) * 128 + c];
    }
    __syncthreads();
    int w = tid >> 5, l = tid & 31;
    for (int m = w; m < 20; m += 8) {
        float re = 0.f, im = 0.f;
        int idx = 0;
        #pragma unroll 8
        for (int a = 0; a < 128; a++) {
            float xv = xs[l][a];
            float2 t = stw[idx];
            re = fmaf(xv, t.x, re);
            im = fmaf(xv, t.y, im);
            idx = (idx + m) & 127;
        }
        g_xf[(m * 128 + j) * 256 + zi0 + l] = make_float2(re, im);
    }
}

__global__ void kx2() {
    __shared__ float sw[128];
    int lmh = blockIdx.x, zi = threadIdx.x;
    if (zi < 128) sw[zi] = g_ws2[lmh * 128 + zi];
    __syncthreads();
    int l = 0; while ((l + 1) * (l + 2) / 2 <= lmh) l++;
    int m = lmh - l * (l + 1) / 2;
    const float2* base = g_xf + m * 128 * 256;
    float ar = 0.f, ai = 0.f;
    for (int j = 0; j < 128; j++) {
        float w = sw[j];
        float2 v = base[j * 256 + zi];
        ar = fmaf(w, v.x, ar);
        ai = fmaf(w, v.y, ai);
    }
    g_xl[lmh * 256 + zi] = make_float2(ar, ai);
}

__global__ void kx3() {
    __shared__ float2 sx[256];
    __shared__ float2 sy[512];
    int t = blockIdx.x, tid = threadIdx.x;
    int l = 0; while (c_T[l + 1] <= t) l++;
    int r = t - c_T[l];
    int m = r / (2*l + 1), ni = r % (2*l + 1);
    int lmh = l * (l + 1) / 2 + m;
    int lmf = l * l + ni;
    if (tid < 256) sx[tid] = g_xl[lmh * 256 + tid];
    sy[tid] = g_y[lmf * 512 + tid];
    __syncthreads();
    int z = tid >> 5, o = tid & 31;
    float ar = 0.f, ai = 0.f;
    #pragma unroll
    for (int i = 0; i < 16; i++) {
        float2 xv = sx[z * 16 + i];
        float2 yv = sy[i * 32 + o];
        ar += xv.x * yv.x + xv.y * yv.y;
        ai += xv.y * yv.x - xv.x * yv.y;
    }
    g_zl[t * 512 + tid] = make_float2(ar, ai);
}

// fused synthesis: planar smem, register twiddle rotators, parity-folded output
__global__ void __launch_bounds__(320) kx4(float* __restrict__ out, const float* __restrict__ bias) {
    __shared__ __align__(16) float sOmr[8][44];
    __shared__ __align__(16) float sOmi[8][44];
    __shared__ __align__(16) float sGr [8][44];
    __shared__ __align__(16) float sGi [8][44];
    __shared__ float2 se[40];
    int tid = threadIdx.x;
    int zo0 = blockIdx.x * 8;                 // zo fastest across blocks (R3 ordering)
    int b   = blockIdx.y;
    if (tid < 40) se[tid] = g_e40f[tid];

    // stage-1 role
    int nidx = tid >> 3, zol1 = tid & 7;
    // stage-2 role
    int g2 = tid >> 3, zol2 = tid & 7;
    // stage-3 role
    int a3 = tid >> 4;                        // 0..19
    int rem = tid & 15;
    int zol3 = rem >> 1, gh = rem & 1;        // gh: g-half (0..1)

    if (nidx == 39) { sOmr[zol1][39] = 0.f; sOmi[zol1][39] = 0.f; }
    __syncthreads();

    // m-invariant stage-2 rotators: c_j = e^{i*2pi*g*(j-19)/40}, w4 = e^{i*2pi*4g/40}
    float2 c0 = se[(21 * g2) % 40];
    float2 c1 = se[(22 * g2) % 40];
    float2 c2 = se[(23 * g2) % 40];
    float2 c3 = se[(24 * g2) % 40];
    float2 w4 = se[( 4 * g2) % 40];

    float fP[20], fM[20];
    #pragma unroll
    for (int g = 0; g < 20; g++) { fP[g] = 0.f; fM[g] = 0.f; }

    for (int m = 0; m < 20; m++) {
        // ---- stage 1: Om[n] = sum_l dinv[b][l,m,n] * zl[l,m,n][zo]
        if (nidx < 39) {
            int n = nidx - 19;
            int an = n < 0 ? -n : n;
            int lmin = m > an ? m : an;
            float orr = 0.f, oii = 0.f;
            int tt = c_T[lmin] + m * (2*lmin + 1) + (n + lmin);
            for (int l = lmin; l < 20; l++) {
                float d = g_dinv[b * 5530 + tt];
                float2 zv = g_zl[(size_t)tt * 512 + zo0 + zol1];
                orr = fmaf(d, zv.x, orr);
                oii = fmaf(d, zv.y, oii);
                tt += (l + 1) * (2*l + 1) + 2*m + 1;
            }
            sOmr[zol1][nidx] = orr;
            sOmi[zol1][nidx] = oii;
        }
        __syncthreads();
        // ---- stage 2: G[g] = sum_n Om[n] e^{+i 2pi g n /40}, rotators in regs
        {
            float r0x = c0.x, r0y = c0.y, r1x = c1.x, r1y = c1.y;
            float r2x = c2.x, r2y = c2.y, r3x = c3.x, r3y = c3.y;
            float Gr = 0.f, Gi = 0.f;
            const float4* omr4 = (const float4*)&sOmr[zol2][0];
            const float4* omi4 = (const float4*)&sOmi[zol2][0];
            #pragma unroll
            for (int q = 0; q < 10; q++) {
                float4 orv = omr4[q];
                float4 oiv = omi4[q];
                Gr = fmaf(orv.x, r0x, Gr); Gr = fmaf(-oiv.x, r0y, Gr);
                Gi = fmaf(orv.x, r0y, Gi); Gi = fmaf( oiv.x, r0x, Gi);
                Gr = fmaf(orv.y, r1x, Gr); Gr = fmaf(-oiv.y, r1y, Gr);
                Gi = fmaf(orv.y, r1y, Gi); Gi = fmaf( oiv.y, r1x, Gi);
                Gr = fmaf(orv.z, r2x, Gr); Gr = fmaf(-oiv.z, r2y, Gr);
                Gi = fmaf(orv.z, r2y, Gi); Gi = fmaf( oiv.z, r2x, Gi);
                Gr = fmaf(orv.w, r3x, Gr); Gr = fmaf(-oiv.w, r3y, Gr);
                Gi = fmaf(orv.w, r3y, Gi); Gi = fmaf( oiv.w, r3x, Gi);
                float t;
                t = r0x * w4.x - r0y * w4.y; r0y = fmaf(r0x, w4.y, r0y * w4.x); r0x = t;
                t = r1x * w4.x - r1y * w4.y; r1y = fmaf(r1x, w4.y, r1y * w4.x); r1x = t;
                t = r2x * w4.x - r2y * w4.y; r2y = fmaf(r2x, w4.y, r2y * w4.x); r2x = t;
                t = r3x * w4.x - r3y * w4.y; r3y = fmaf(r3x, w4.y, r3y * w4.x); r3x = t;
            }
            __syncthreads();                 // sOm readers done before reuse; also guards sG
            sGr[zol2][g2] = Gr;
            sGi[zol2][g2] = Gi;
        }
        __syncthreads();
        // ---- stage 3: fP/fM[g] += w_m Re( e^{i 2pi m a/40} G[g] ), parity by m
        {
            float2 e = se[(m * a3) % 40];
            float w = (m == 0) ? 1.f : 2.f;
            float wc = w * e.x, ws = w * e.y;
            const float4* gr4 = (const float4*)&sGr[zol3][gh * 20];
            const float4* gi4 = (const float4*)&sGi[zol3][gh * 20];
            if ((m & 1) == 0) {
                #pragma unroll
                for (int q = 0; q < 5; q++) {
                    float4 gr = gr4[q], gi = gi4[q];
                    fP[4*q  ] = fmaf(wc, gr.x, fmaf(-ws, gi.x, fP[4*q  ]));
                    fP[4*q+1] = fmaf(wc, gr.y, fmaf(-ws, gi.y, fP[4*q+1]));
                    fP[4*q+2] = fmaf(wc, gr.z, fmaf(-ws, gi.z, fP[4*q+2]));
                    fP[4*q+3] = fmaf(wc, gr.w, fmaf(-ws, gi.w, fP[4*q+3]));
                }
            } else {
                #pragma unroll
                for (int q = 0; q < 5; q++) {
                    float4 gr = gr4[q], gi = gi4[q];
                    fM[4*q  ] = fmaf(wc, gr.x, fmaf(-ws, gi.x, fM[4*q  ]));
                    fM[4*q+1] = fmaf(wc, gr.y, fmaf(-ws, gi.y, fM[4*q+1]));
                    fM[4*q+2] = fmaf(wc, gr.z, fmaf(-ws, gi.z, fM[4*q+2]));
                    fM[4*q+3] = fmaf(wc, gr.w, fmaf(-ws, gi.w, fM[4*q+3]));
                }
            }
        }
        __syncthreads();
    }

    // ---- write: f[a] = fP+fM, f[a+20] = fP-fM
    int zo = zo0 + zol3;
    float bv = bias[zo & 31];
    float* op  = out + ((size_t)zo * 40 + b) * 1600 + a3 * 40 + gh * 20;
    float* op2 = op + 800;                    // (a3+20)*40
    float4* o4a = (float4*)op;
    float4* o4b = (float4*)op2;
    #pragma unroll
    for (int q = 0; q < 5; q++) {
        o4a[q] = make_float4(fP[4*q]   + fM[4*q]   + bv, fP[4*q+1] + fM[4*q+1] + bv,
                             fP[4*q+2] + fM[4*q+2] + bv, fP[4*q+3] + fM[4*q+3] + bv);
        o4b[q] = make_float4(fP[4*q]   - fM[4*q]   + bv, fP[4*q+1] - fM[4*q+1] + bv,
                             fP[4*q+2] - fM[4*q+2] + bv, fP[4*q+3] - fM[4*q+3] + bv);
    }
}

// ---------------- launch ----------------
extern "C" void kernel_launch(void* const* d_in, const int* in_sizes, int n_in,
                              void* d_out, int out_size) {
    const float* x    = (const float*)d_in[0];
    const float* ker  = (const float*)d_in[1];
    const float* bias = (const float*)d_in[2];
    float* out = (float*)d_out;

    k_init<<<1, 128>>>();
    k_sd  <<<210 + 1844, 128>>>();
    k_y   <<<400, 512>>>(ker);

    kx1<<<dim3(128, 8), 256>>>(x);
    kx2<<<210, 256>>>();
    kx3<<<5530, 512>>>();
    kx4<<<dim3(64, 40), 320>>>(out, bias);
}

// round 6
// speedup vs baseline: 1.8561x; 1.5048x over previous
#include <cuda_runtime.h>
#include <math.h>

#define PI_D 3.141592653589793238462643383279502884

// ---------------- constant / scratch device globals ----------------
__device__ double g_lg[64];
__device__ double g_wq[128];
__device__ float2 g_tw128[128];
__device__ float2 g_e40f[40];

__device__ float  g_ws2 [210*128];
__device__ float  g_dinv[40*5530];
__device__ float2 g_y   [400*512];
__device__ float2 g_xf  [20*128*256];
__device__ float2 g_xl  [210*256];
__device__ float2 g_zl  [5530*512];

__device__ const int c_T[21] = {0,1,7,22,50,95,161,252,372,525,715,946,1222,1547,
                                1925,2360,2856,3417,4047,4750,5530};

__device__ double dpow_int(double x, int e) { double r = 1.0; for (int i = 0; i < e; i++) r *= x; return r; }

__device__ double wig_pow(int l, int m, int n, double cb, double sb) {
    int s0 = max(0, n - m), s1 = min(l + n, l - m);
    if (s1 < s0) return 0.0;
    double pref = 0.5 * (g_lg[l+m] + g_lg[l-m] + g_lg[l+n] + g_lg[l-n]);
    double C = exp(pref - (g_lg[l+n-s0] + g_lg[s0] + g_lg[m-n+s0] + g_lg[l-m-s0]));
    double sg = ((m - n + s0) & 1) ? -1.0 : 1.0;
    int A = 2*l + n - m - 2*s0, B = m - n + 2*s0;
    double cbA = dpow_int(cb, A), sbB = dpow_int(sb, B);
    double ci = 1.0 / (cb * cb), s2 = sb * sb;
    double val = 0.0;
    for (int s = s0; s <= s1; s++) {
        val += sg * C * cbA * sbB;
        C  *= (double)((l + n - s) * (l - m - s)) / (double)((s + 1) * (m - n + s + 1));
        sg = -sg; cbA *= ci; sbB *= s2;
    }
    return val;
}

// ---------------- setup kernels ----------------
__global__ void k_init() {
    int t = threadIdx.x;  // 128
    if (t == 0) {
        double a = 0.0; g_lg[0] = 0.0;
        for (int k = 1; k < 64; k++) { a += log((double)k); g_lg[k] = a; }
    }
    {
        double th = PI_D * (2*t + 1) / 256.0;
        double s = 0.0;
        for (int k = 0; k < 64; k++) s += sin((2*k + 1) * th) / (double)(2*k + 1);
        g_wq[t] = (2.0 / 64.0) * sin(th) * s;
        double ang = 2.0 * PI_D * t / 128.0;
        g_tw128[t] = make_float2((float)cos(ang), (float)(-sin(ang)));
    }
    if (t < 40) {
        double ang = 2.0 * PI_D * t / 40.0;
        g_e40f[t] = make_float2((float)cos(ang), (float)sin(ang));
    }
}

__global__ void k_sd() {
    __shared__ double scoef[3][24];
    int blk = blockIdx.x;
    int tid = threadIdx.x;
    if (blk < 210) {
        int lmh = blk;
        int l = 0; while ((l + 1) * (l + 2) / 2 <= lmh) l++;
        int m = lmh - l * (l + 1) / 2;
        int s1 = l - m;
        if (tid == 0) {
            double pref = 0.5 * (g_lg[l+m] + g_lg[l-m]) + g_lg[l];
            double C = exp(pref - (g_lg[l] + g_lg[m] + g_lg[l-m]));
            double sg = (m & 1) ? -1.0 : 1.0;
            for (int s = 0; s <= s1; s++) {
                scoef[0][s] = sg * C;
                C *= (double)((l - s) * (l - m - s)) / (double)((s + 1) * (m + s + 1));
                sg = -sg;
            }
        }
        __syncthreads();
        int j = tid;
        double th = PI_D * (2*j + 1) / 256.0;
        double cb = cos(0.5 * th), sb = sin(0.5 * th);
        double cbA = dpow_int(cb, 2*l - m), sbB = dpow_int(sb, m);
        double ci = 1.0 / (cb * cb), s2 = sb * sb;
        double val = 0.0;
        for (int s = 0; s <= s1; s++) { val += scoef[0][s] * cbA * sbB; cbA *= ci; sbB *= s2; }
        g_ws2[lmh * 128 + j] = (float)(val * g_wq[j]);
    } else {
        int t0 = (blk - 210) * 3;
        if (tid < 3 && t0 + tid < 5530) {
            int t = t0 + tid;
            int l = 0; while (c_T[l + 1] <= t) l++;
            int r = t - c_T[l];
            int m = r / (2*l + 1);
            int n = r % (2*l + 1) - l;
            int s0 = max(0, n - m), s1 = min(l + n, l - m);
            double pref = 0.5 * (g_lg[l+m] + g_lg[l-m] + g_lg[l+n] + g_lg[l-n]);
            double C = exp(pref - (g_lg[l+n-s0] + g_lg[s0] + g_lg[m-n+s0] + g_lg[l-m-s0]));
            double sg = ((m - n + s0) & 1) ? -1.0 : 1.0;
            for (int s = s0; s <= s1; s++) {
                scoef[tid][s - s0] = sg * C;
                C *= (double)((l + n - s) * (l - m - s)) / (double)((s + 1) * (m - n + s + 1));
                sg = -sg;
            }
        }
        __syncthreads();
        int sub = tid / 40, b = tid % 40;
        int t = t0 + sub;
        if (sub < 3 && t < 5530) {
            int l = 0; while (c_T[l + 1] <= t) l++;
            int r = t - c_T[l];
            int m = r / (2*l + 1);
            int n = r % (2*l + 1) - l;
            int s0 = max(0, n - m), s1 = min(l + n, l - m);
            double th = PI_D * (2*b + 1) / 80.0;
            double cb = cos(0.5 * th), sb = sin(0.5 * th);
            int A0 = 2*l + n - m - 2*s0, B0 = m - n + 2*s0;
            double cbA = dpow_int(cb, A0), sbB = dpow_int(sb, B0);
            double ci = 1.0 / (cb * cb), s2 = sb * sb;
            double val = 0.0;
            int nt = s1 - s0;
            for (int s = 0; s <= nt; s++) { val += scoef[sub][s] * cbA * sbB; cbA *= ci; sbB *= s2; }
            g_dinv[b * 5530 + t] = (float)(val * (double)(2*l + 1));
        }
    }
}

__global__ void k_y(const float* __restrict__ ker) {
    __shared__ float2 sFk[24];
    int lmf = blockIdx.x, io = threadIdx.x;                   // 400 x 512
    int l = 0; while ((l + 1) * (l + 1) <= lmf) l++;
    int m = lmf - l * l - l;
    if (io < 24) {
        double beta  = (io / 8 + 1) * (PI_D / 24.0);
        double alpha = (io % 8) * (PI_D / 4.0);
        double cb = cos(0.5 * beta), sb = sin(0.5 * beta);
        double d = wig_pow(l, m, 0, cb, sb);
        double sn, cn; sincos(-(double)m * alpha, &sn, &cn);
        sFk[io] = make_float2((float)(d * cn), (float)(d * sn));
    }
    __syncthreads();
    const float sc = 0.008164965809277261f;
    float ar = 0.f, ai = 0.f;
    #pragma unroll
    for (int p = 0; p < 24; p++) {
        float k = ker[io * 24 + p];
        ar = fmaf(k, sFk[p].x, ar);
        ai = fmaf(k, sFk[p].y, ai);
    }
    g_y[lmf * 512 + io] = make_float2(sc * ar, sc * ai);
}

// ---------------- main pipeline ----------------
__global__ void kx1(const float* __restrict__ x) {
    __shared__ float  xs[32][129];
    __shared__ float2 stw[128];
    int tid = threadIdx.x;
    int j = blockIdx.x;
    int zi0 = blockIdx.y * 32;
    if (tid < 128) stw[tid] = g_tw128[tid];
    for (int i = tid; i < 4096; i += 256) {
        int r = i >> 7, c = i & 127;
        xs[r][c] = x[((size_t)(zi0 + r) * 128 + j) * 128 + c];
    }
    __syncthreads();
    int w = tid >> 5, l = tid & 31;
    for (int m = w; m < 20; m += 8) {
        float re = 0.f, im = 0.f;
        int idx = 0;
        #pragma unroll 8
        for (int a = 0; a < 128; a++) {
            float xv = xs[l][a];
            float2 t = stw[idx];
            re = fmaf(xv, t.x, re);
            im = fmaf(xv, t.y, im);
            idx = (idx + m) & 127;
        }
        g_xf[(m * 128 + j) * 256 + zi0 + l] = make_float2(re, im);
    }
}

__global__ void kx2() {
    __shared__ float sw[128];
    int lmh = blockIdx.x, zi = threadIdx.x;
    if (zi < 128) sw[zi] = g_ws2[lmh * 128 + zi];
    __syncthreads();
    int l = 0; while ((l + 1) * (l + 2) / 2 <= lmh) l++;
    int m = lmh - l * (l + 1) / 2;
    const float2* base = g_xf + m * 128 * 256;
    float ar = 0.f, ai = 0.f;
    for (int j = 0; j < 128; j++) {
        float w = sw[j];
        float2 v = base[j * 256 + zi];
        ar = fmaf(w, v.x, ar);
        ai = fmaf(w, v.y, ai);
    }
    g_xl[lmh * 256 + zi] = make_float2(ar, ai);
}

__global__ void kx3() {
    __shared__ float2 sx[256];
    __shared__ float2 sy[512];
    int t = blockIdx.x, tid = threadIdx.x;
    int l = 0; while (c_T[l + 1] <= t) l++;
    int r = t - c_T[l];
    int m = r / (2*l + 1), ni = r % (2*l + 1);
    int lmh = l * (l + 1) / 2 + m;
    int lmf = l * l + ni;
    if (tid < 256) sx[tid] = g_xl[lmh * 256 + tid];
    sy[tid] = g_y[lmf * 512 + tid];
    __syncthreads();
    int z = tid >> 5, o = tid & 31;
    float ar = 0.f, ai = 0.f;
    #pragma unroll
    for (int i = 0; i < 16; i++) {
        float2 xv = sx[z * 16 + i];
        float2 yv = sy[i * 32 + o];
        ar += xv.x * yv.x + xv.y * yv.y;
        ai += xv.y * yv.x - xv.x * yv.y;
    }
    g_zl[t * 512 + tid] = make_float2(ar, ai);
}

// fused synthesis v6: b-tile=2, n-parity folded stage2 with register rotators,
// parity-split planar smem (28-float rows, conflict-free LDS.128), m-parity output fold.
__global__ void __launch_bounds__(320) kx4(float* __restrict__ out, const float* __restrict__ bias) {
    __shared__ float sOm[2][2][2][8][28];   // [n-parity][re/im][b][zol][k]
    __shared__ float sS [2][2][2][8][28];   // [n-parity][re/im][b][zol][gp]
    __shared__ float2 se[40];
    int tid = threadIdx.x;
    int zo0 = blockIdx.x * 8;
    int b0  = blockIdx.y * 2;
    if (tid < 40) se[tid] = g_e40f[tid];

    // stage-1 role
    int nidx = tid >> 3, zol1 = tid & 7;
    // stage-2 role: parity is warp-uniform (tid>=160 -> odd-n partial)
    int par2 = (tid >= 160) ? 1 : 0;
    int r2   = tid - 160 * par2;
    int g2   = r2 >> 3, zol2 = r2 & 7;
    // stage-3 role
    int a3 = tid >> 4;
    int rem = tid & 15;
    int zol3 = rem >> 1, gh = rem & 1;
    float sgn = gh ? -1.f : 1.f;

    // zero the even-parity pad slot k=19 (never written by stage1)
    if (tid < 32) {
        int cc = tid & 1, bb = (tid >> 1) & 1, zz = (tid >> 2) & 7;
        sOm[0][cc][bb][zz][19] = 0.f;
    }
    __syncthreads();

    // m-invariant stage-2 rotators: c_j = e^{i*2pi*(n0+2j)*g/40}, step w8 = e^{i*2pi*8g/40}
    int basek = par2 ? 21 : 22;               // n0 = -19 (odd) / -18 (even), mod 40
    float2 cc0 = se[((basek    ) * g2) % 40];
    float2 cc1 = se[((basek + 2) * g2) % 40];
    float2 cc2 = se[((basek + 4) * g2) % 40];
    float2 cc3 = se[((basek + 6) * g2) % 40];
    float2 w8  = se[(8 * g2) % 40];

    float f0P[20], f0M[20], f1P[20], f1M[20];
    #pragma unroll
    for (int g = 0; g < 20; g++) { f0P[g] = 0.f; f0M[g] = 0.f; f1P[g] = 0.f; f1M[g] = 0.f; }

    for (int m = 0; m < 20; m++) {
        // ---- stage 1: Om[n] = sum_l dinv[b][l,m,n] * zl[l,m,n][zo], 2 b's
        if (nidx < 39) {
            int n = nidx - 19;
            int an = n < 0 ? -n : n;
            int lmin = m > an ? m : an;
            float o0r = 0.f, o0i = 0.f, o1r = 0.f, o1i = 0.f;
            int tt = c_T[lmin] + m * (2*lmin + 1) + (n + lmin);
            for (int l = lmin; l < 20; l++) {
                float d0 = g_dinv[b0 * 5530 + tt];
                float d1 = g_dinv[(b0 + 1) * 5530 + tt];
                float2 zv = g_zl[(size_t)tt * 512 + zo0 + zol1];
                o0r = fmaf(d0, zv.x, o0r);
                o0i = fmaf(d0, zv.y, o0i);
                o1r = fmaf(d1, zv.x, o1r);
                o1i = fmaf(d1, zv.y, o1i);
                tt += (l + 1) * (2*l + 1) + 2*m + 1;
            }
            int p = n & 1;
            int k = (n + 18 + p) >> 1;
            sOm[p][0][0][zol1][k] = o0r;
            sOm[p][1][0][zol1][k] = o0i;
            sOm[p][0][1][zol1][k] = o1r;
            sOm[p][1][1][zol1][k] = o1i;
        }
        __syncthreads();
        // ---- stage 2: parity partial S_par[g] = sum_{k} Om_par[k] * c(k), 2 b's
        {
            float q0x = cc0.x, q0y = cc0.y, q1x = cc1.x, q1y = cc1.y;
            float q2x = cc2.x, q2y = cc2.y, q3x = cc3.x, q3y = cc3.y;
            float S0r = 0.f, S0i = 0.f, S1r = 0.f, S1i = 0.f;
            const float4* A0r = (const float4*)&sOm[par2][0][0][zol2][0];
            const float4* A0i = (const float4*)&sOm[par2][1][0][zol2][0];
            const float4* A1r = (const float4*)&sOm[par2][0][1][zol2][0];
            const float4* A1i = (const float4*)&sOm[par2][1][1][zol2][0];
            #pragma unroll
            for (int q = 0; q < 5; q++) {
                float4 ar0 = A0r[q], ai0 = A0i[q], ar1 = A1r[q], ai1 = A1i[q];
                S0r = fmaf(ar0.x, q0x, S0r); S0r = fmaf(-ai0.x, q0y, S0r);
                S0i = fmaf(ar0.x, q0y, S0i); S0i = fmaf( ai0.x, q0x, S0i);
                S1r = fmaf(ar1.x, q0x, S1r); S1r = fmaf(-ai1.x, q0y, S1r);
                S1i = fmaf(ar1.x, q0y, S1i); S1i = fmaf( ai1.x, q0x, S1i);
                S0r = fmaf(ar0.y, q1x, S0r); S0r = fmaf(-ai0.y, q1y, S0r);
                S0i = fmaf(ar0.y, q1y, S0i); S0i = fmaf( ai0.y, q1x, S0i);
                S1r = fmaf(ar1.y, q1x, S1r); S1r = fmaf(-ai1.y, q1y, S1r);
                S1i = fmaf(ar1.y, q1y, S1i); S1i = fmaf( ai1.y, q1x, S1i);
                S0r = fmaf(ar0.z, q2x, S0r); S0r = fmaf(-ai0.z, q2y, S0r);
                S0i = fmaf(ar0.z, q2y, S0i); S0i = fmaf( ai0.z, q2x, S0i);
                S1r = fmaf(ar1.z, q2x, S1r); S1r = fmaf(-ai1.z, q2y, S1r);
                S1i = fmaf(ar1.z, q2y, S1i); S1i = fmaf( ai1.z, q2x, S1i);
                S0r = fmaf(ar0.w, q3x, S0r); S0r = fmaf(-ai0.w, q3y, S0r);
                S0i = fmaf(ar0.w, q3y, S0i); S0i = fmaf( ai0.w, q3x, S0i);
                S1r = fmaf(ar1.w, q3x, S1r); S1r = fmaf(-ai1.w, q3y, S1r);
                S1i = fmaf(ar1.w, q3y, S1i); S1i = fmaf( ai1.w, q3x, S1i);
                float t;
                t = q0x * w8.x - q0y * w8.y; q0y = fmaf(q0x, w8.y, q0y * w8.x); q0x = t;
                t = q1x * w8.x - q1y * w8.y; q1y = fmaf(q1x, w8.y, q1y * w8.x); q1x = t;
                t = q2x * w8.x - q2y * w8.y; q2y = fmaf(q2x, w8.y, q2y * w8.x); q2x = t;
                t = q3x * w8.x - q3y * w8.y; q3y = fmaf(q3x, w8.y, q3y * w8.x); q3x = t;
            }
            __syncthreads();                 // Om readers done; guards sS reuse from prev m
            sS[par2][0][0][zol2][g2] = S0r;
            sS[par2][1][0][zol2][g2] = S0i;
            sS[par2][0][1][zol2][g2] = S1r;
            sS[par2][1][1][zol2][g2] = S1i;
        }
        __syncthreads();
        // ---- stage 3: f += w_m Re( e^{i 2pi m a/40} (Se + sgn*So) ), split by m parity
        {
            float2 e = se[(m * a3) % 40];
            float w = (m == 0) ? 1.f : 2.f;
            float wc = w * e.x, ws = w * e.y;
            const float4* Er0 = (const float4*)&sS[0][0][0][zol3][0];
            const float4* Ei0 = (const float4*)&sS[0][1][0][zol3][0];
            const float4* Or0 = (const float4*)&sS[1][0][0][zol3][0];
            const float4* Oi0 = (const float4*)&sS[1][1][0][zol3][0];
            const float4* Er1 = (const float4*)&sS[0][0][1][zol3][0];
            const float4* Ei1 = (const float4*)&sS[0][1][1][zol3][0];
            const float4* Or1 = (const float4*)&sS[1][0][1][zol3][0];
            const float4* Oi1 = (const float4*)&sS[1][1][1][zol3][0];
            if ((m & 1) == 0) {
                #pragma unroll
                for (int q = 0; q < 5; q++) {
                    float4 er = Er0[q], ei = Ei0[q], orv = Or0[q], oiv = Oi0[q];
                    f0P[4*q  ] = fmaf(wc, fmaf(sgn, orv.x, er.x), fmaf(-ws, fmaf(sgn, oiv.x, ei.x), f0P[4*q  ]));
                    f0P[4*q+1] = fmaf(wc, fmaf(sgn, orv.y, er.y), fmaf(-ws, fmaf(sgn, oiv.y, ei.y), f0P[4*q+1]));
                    f0P[4*q+2] = fmaf(wc, fmaf(sgn, orv.z, er.z), fmaf(-ws, fmaf(sgn, oiv.z, ei.z), f0P[4*q+2]));
                    f0P[4*q+3] = fmaf(wc, fmaf(sgn, orv.w, er.w), fmaf(-ws, fmaf(sgn, oiv.w, ei.w), f0P[4*q+3]));
                    er = Er1[q]; ei = Ei1[q]; orv = Or1[q]; oiv = Oi1[q];
                    f1P[4*q  ] = fmaf(wc, fmaf(sgn, orv.x, er.x), fmaf(-ws, fmaf(sgn, oiv.x, ei.x), f1P[4*q  ]));
                    f1P[4*q+1] = fmaf(wc, fmaf(sgn, orv.y, er.y), fmaf(-ws, fmaf(sgn, oiv.y, ei.y), f1P[4*q+1]));
                    f1P[4*q+2] = fmaf(wc, fmaf(sgn, orv.z, er.z), fmaf(-ws, fmaf(sgn, oiv.z, ei.z), f1P[4*q+2]));
                    f1P[4*q+3] = fmaf(wc, fmaf(sgn, orv.w, er.w), fmaf(-ws, fmaf(sgn, oiv.w, ei.w), f1P[4*q+3]));
                }
            } else {
                #pragma unroll
                for (int q = 0; q < 5; q++) {
                    float4 er = Er0[q], ei = Ei0[q], orv = Or0[q], oiv = Oi0[q];
                    f0M[4*q  ] = fmaf(wc, fmaf(sgn, orv.x, er.x), fmaf(-ws, fmaf(sgn, oiv.x, ei.x), f0M[4*q  ]));
                    f0M[4*q+1] = fmaf(wc, fmaf(sgn, orv.y, er.y), fmaf(-ws, fmaf(sgn, oiv.y, ei.y), f0M[4*q+1]));
                    f0M[4*q+2] = fmaf(wc, fmaf(sgn, orv.z, er.z), fmaf(-ws, fmaf(sgn, oiv.z, ei.z), f0M[4*q+2]));
                    f0M[4*q+3] = fmaf(wc, fmaf(sgn, orv.w, er.w), fmaf(-ws, fmaf(sgn, oiv.w, ei.w), f0M[4*q+3]));
                    er = Er1[q]; ei = Ei1[q]; orv = Or1[q]; oiv = Oi1[q];
                    f1M[4*q  ] = fmaf(wc, fmaf(sgn, orv.x, er.x), fmaf(-ws, fmaf(sgn, oiv.x, ei.x), f1M[4*q  ]));
                    f1M[4*q+1] = fmaf(wc, fmaf(sgn, orv.y, er.y), fmaf(-ws, fmaf(sgn, oiv.y, ei.y), f1M[4*q+1]));
                    f1M[4*q+2] = fmaf(wc, fmaf(sgn, orv.z, er.z), fmaf(-ws, fmaf(sgn, oiv.z, ei.z), f1M[4*q+2]));
                    f1M[4*q+3] = fmaf(wc, fmaf(sgn, orv.w, er.w), fmaf(-ws, fmaf(sgn, oiv.w, ei.w), f1M[4*q+3]));
                }
            }
        }
        __syncthreads();
    }

    // ---- write: rows a (fP+fM) and a+20 (fP-fM), columns gh*20..gh*20+19
    int zo = zo0 + zol3;
    float bv = bias[zo & 31];
    float* base0 = out + ((size_t)zo * 40 + b0) * 1600 + a3 * 40 + gh * 20;
    float4* oa0 = (float4*)base0;
    float4* ob0 = (float4*)(base0 + 800);
    float4* oa1 = (float4*)(base0 + 1600);
    float4* ob1 = (float4*)(base0 + 2400);
    #pragma unroll
    for (int q = 0; q < 5; q++) {
        oa0[q] = make_float4(f0P[4*q]   + f0M[4*q]   + bv, f0P[4*q+1] + f0M[4*q+1] + bv,
                             f0P[4*q+2] + f0M[4*q+2] + bv, f0P[4*q+3] + f0M[4*q+3] + bv);
        ob0[q] = make_float4(f0P[4*q]   - f0M[4*q]   + bv, f0P[4*q+1] - f0M[4*q+1] + bv,
                             f0P[4*q+2] - f0M[4*q+2] + bv, f0P[4*q+3] - f0M[4*q+3] + bv);
        oa1[q] = make_float4(f1P[4*q]   + f1M[4*q]   + bv, f1P[4*q+1] + f1M[4*q+1] + bv,
                             f1P[4*q+2] + f1M[4*q+2] + bv, f1P[4*q+3] + f1M[4*q+3] + bv);
        ob1[q] = make_float4(f1P[4*q]   - f1M[4*q]   + bv, f1P[4*q+1] - f1M[4*q+1] + bv,
                             f1P[4*q+2] - f1M[4*q+2] + bv, f1P[4*q+3] - f1M[4*q+3] + bv);
    }
}

// ---------------- launch ----------------
extern "C" void kernel_launch(void* const* d_in, const int* in_sizes, int n_in,
                              void* d_out, int out_size) {
    const float* x    = (const float*)d_in[0];
    const float* ker  = (const float*)d_in[1];
    const float* bias = (const float*)d_in[2];
    float* out = (float*)d_out;

    k_init<<<1, 128>>>();
    k_sd  <<<210 + 1844, 128>>>();
    k_y   <<<400, 512>>>(ker);

    kx1<<<dim3(128, 8), 256>>>(x);
    kx2<<<210, 256>>>();
    kx3<<<5530, 512>>>();
    kx4<<<dim3(64, 20), 320>>>(out, bias);
}